// round 2
// baseline (speedup 1.0000x reference)
#include <cuda_runtime.h>
#include <math.h>

// Problem shapes (fixed by setup_inputs)
#define NQ 2048
#define NS 64
#define LL 8
#define DD 576
#define QF (NQ * LL)   // 16384 query frames
#define SF (NS * LL)   // 512 support frames
#define EPSILON 0.01f

// -------- scratch (device globals; no allocation allowed) --------
__device__ float g_P[(size_t)QF * SF];  // 33.5 MB frame-dist matrix [QF, SF]
__device__ float g_qn[QF];
__device__ float g_sn[SF];

// ======================= norms =======================
// One warp per row; rows [0,QF) are query frames, [QF, QF+SF) support frames.
__global__ void norms_kernel(const float* __restrict__ Q,
                             const float* __restrict__ S) {
    int warp = (blockIdx.x * blockDim.x + threadIdx.x) >> 5;
    int lane = threadIdx.x & 31;
    if (warp >= QF + SF) return;
    const float* row = (warp < QF) ? (Q + (size_t)warp * DD)
                                   : (S + (size_t)(warp - QF) * DD);
    float s = 0.f;
    for (int k = lane; k < DD; k += 32) {
        float v = row[k];
        s = fmaf(v, v, s);
    }
#pragma unroll
    for (int o = 16; o > 0; o >>= 1) s += __shfl_down_sync(0xffffffffu, s, o);
    if (lane == 0) {
        float n = sqrtf(s);
        if (warp < QF) g_qn[warp] = n;
        else           g_sn[warp - QF] = n;
    }
}

// ======================= dist GEMM =======================
// P[i,j] = 1 - (Q_i . S_j) / (|Q_i||S_j| + eps)
// Tiles: BM=BN=64, BK=32, 256 threads, 4x4 register micro-tile per thread.
#define BM 64
#define BN 64
#define BK 32

__global__ __launch_bounds__(256) void gemm_dist_kernel(
    const float* __restrict__ Q, const float* __restrict__ S) {
    __shared__ float As[BK][BM + 4];
    __shared__ float Bs[BK][BN + 4];

    const int tid  = threadIdx.x;
    const int brow = blockIdx.x * BM;  // query-frame base
    const int bcol = blockIdx.y * BN;  // support-frame base
    const int ty   = tid >> 4;         // 0..15
    const int tx   = tid & 15;         // 0..15

    float acc[4][4];
#pragma unroll
    for (int i = 0; i < 4; i++)
#pragma unroll
        for (int j = 0; j < 4; j++) acc[i][j] = 0.f;

    for (int k0 = 0; k0 < DD; k0 += BK) {
        // Load 64x32 tiles of Q and S (row-major, K contiguous) into
        // k-major smem so the compute loop reads float4 along M/N.
#pragma unroll
        for (int r = 0; r < 2; r++) {
            int t   = tid + r * 256;     // 0..511
            int row = t >> 3;            // 0..63
            int kv  = (t & 7) << 2;      // 0,4,...,28
            float4 a = *(const float4*)(Q + (size_t)(brow + row) * DD + k0 + kv);
            As[kv + 0][row] = a.x; As[kv + 1][row] = a.y;
            As[kv + 2][row] = a.z; As[kv + 3][row] = a.w;
            float4 b = *(const float4*)(S + (size_t)(bcol + row) * DD + k0 + kv);
            Bs[kv + 0][row] = b.x; Bs[kv + 1][row] = b.y;
            Bs[kv + 2][row] = b.z; Bs[kv + 3][row] = b.w;
        }
        __syncthreads();

#pragma unroll
        for (int kk = 0; kk < BK; kk++) {
            float4 av = *(const float4*)&As[kk][ty << 2];
            float4 bv = *(const float4*)&Bs[kk][tx << 2];
            float a0[4] = {av.x, av.y, av.z, av.w};
            float b0[4] = {bv.x, bv.y, bv.z, bv.w};
#pragma unroll
            for (int i = 0; i < 4; i++)
#pragma unroll
                for (int j = 0; j < 4; j++)
                    acc[i][j] = fmaf(a0[i], b0[j], acc[i][j]);
        }
        __syncthreads();
    }

    float qn[4], sn[4];
#pragma unroll
    for (int i = 0; i < 4; i++) qn[i] = g_qn[brow + (ty << 2) + i];
#pragma unroll
    for (int j = 0; j < 4; j++) sn[j] = g_sn[bcol + (tx << 2) + j];

#pragma unroll
    for (int i = 0; i < 4; i++) {
        int grow = brow + (ty << 2) + i;
#pragma unroll
        for (int j = 0; j < 4; j++) {
            int gcol  = bcol + (tx << 2) + j;
            float den = qn[i] * sn[j] + EPSILON;
            g_P[(size_t)grow * SF + gcol] = 1.f - acc[i][j] / den;
        }
    }
}

// ======================= OTAM DP =======================
// softmin with lbda = 0.5:  m - 0.5*log(sum exp(2*(m - t)))
__device__ __forceinline__ float softmin2(float a, float b) {
    float m = fminf(a, b);
    float s = __expf((m - a) * 2.f) + __expf((m - b) * 2.f);
    return fmaf(-0.5f, __logf(s), m);
}
__device__ __forceinline__ float softmin3(float a, float b, float c) {
    float m = fminf(fminf(a, b), c);
    float s = __expf((m - a) * 2.f) + __expf((m - b) * 2.f) +
              __expf((m - c) * 2.f);
    return fmaf(-0.5f, __logf(s), m);
}

// DP over padded width W=10. Column m in 1..8 maps to dist index m-1; m=9 is
// the zero pad. include_up only at m==1 and m==9 (faithful to reference).
template <bool TR>
__device__ __forceinline__ float otam_dp(const float d[8][8]) {
    float prev[10], cur[10];
    prev[0] = 0.f;
    float run = 0.f;
#pragma unroll
    for (int m = 1; m <= 8; m++) {
        run += TR ? d[m - 1][0] : d[0][m - 1];
        prev[m] = run;
    }
    prev[9] = run;  // + pad zero
#pragma unroll
    for (int l = 1; l < 8; l++) {
        cur[0] = 0.f;
        {
            float dm = TR ? d[0][l] : d[l][0];
            cur[1] = dm + softmin3(prev[0], cur[0], prev[1]);
        }
#pragma unroll
        for (int m = 2; m <= 8; m++) {
            float dm = TR ? d[m - 1][l] : d[l][m - 1];
            cur[m] = dm + softmin2(prev[m - 1], cur[m - 1]);
        }
        cur[9] = softmin3(prev[8], cur[8], prev[9]);
#pragma unroll
        for (int m = 0; m < 10; m++) prev[m] = cur[m];
    }
    return prev[9];
}

__global__ __launch_bounds__(256) void dp_kernel(float* __restrict__ out) {
    int pair = blockIdx.x * blockDim.x + threadIdx.x;
    if (pair >= NQ * NS) return;
    int q = pair >> 6;   // / NS
    int c = pair & 63;   // % NS
    const float* base = g_P + (size_t)q * LL * SF + (size_t)c * LL;

    float d[8][8];
#pragma unroll
    for (int l = 0; l < 8; l++) {
        float4 v0 = *(const float4*)(base + (size_t)l * SF);
        float4 v1 = *(const float4*)(base + (size_t)l * SF + 4);
        d[l][0] = v0.x; d[l][1] = v0.y; d[l][2] = v0.z; d[l][3] = v0.w;
        d[l][4] = v1.x; d[l][5] = v1.y; d[l][6] = v1.z; d[l][7] = v1.w;
    }
    float r = otam_dp<false>(d) + otam_dp<true>(d);
    out[pair] = -r;
}

// ======================= launch =======================
extern "C" void kernel_launch(void* const* d_in, const int* in_sizes, int n_in,
                              void* d_out, int out_size) {
    // support has 64*8*576 = 294912 elems; query has 2048*8*576 = 9437184.
    const float* sup = (const float*)d_in[0];
    const float* qry = (const float*)d_in[1];
    if (n_in >= 2 && in_sizes[0] > in_sizes[1]) {
        const float* t = sup; sup = qry; qry = t;
    }
    float* out = (float*)d_out;

    // 1) norms: one warp per row
    {
        int warps = QF + SF;                 // 16896
        int blocks = (warps + 7) / 8;        // 8 warps / 256-thread block
        norms_kernel<<<blocks, 256>>>(qry, sup);
    }
    // 2) dist GEMM
    {
        dim3 grid(QF / BM, SF / BN);         // (256, 8)
        gemm_dist_kernel<<<grid, 256>>>(qry, sup);
    }
    // 3) OTAM DP, one thread per (query, class) pair
    {
        int blocks = (NQ * NS + 255) / 256;  // 512
        dp_kernel<<<blocks, 256>>>(out);
    }
}

// round 5
// speedup vs baseline: 4.0799x; 4.0799x over previous
#include <cuda_runtime.h>
#include <cuda_bf16.h>
#include <math.h>
#include <stdint.h>

// ---------------- problem shapes ----------------
#define NQ 2048
#define NS 64
#define LL 8
#define DD 576
#define QF (NQ * LL)   // 16384 query frames
#define SF (NS * LL)   // 512 support frames
#define EPSILON 0.01f

// ---------------- GEMM tiling ----------------
#define M_TILE 128
#define N_TILE 128
#define KC 64                               // bf16 K-elems per chunk: 128B rows
#define NCHUNK (DD / KC)                    // 9
#define STAGE_BYTES (M_TILE * 128 + N_TILE * 128)   // 32 KB (A then B)
#define SMEM_NORMS 1024                     // sqn[128] + ssn[128]
#define SMEM_DIST (128 * 129 * 4)           // 66048, overlays stage mem
#define SMEM_TOTAL (SMEM_NORMS + SMEM_DIST) // 67072 (> norms + 2*32KB stages)

// ---------------- scratch (device globals) ----------------
__device__ __nv_bfloat16 g_Qh[(size_t)QF * DD];
__device__ __nv_bfloat16 g_Sh[(size_t)SF * DD];
__device__ float g_qn[QF];
__device__ float g_sn[SF];

// ---------------- PTX helpers (baseline ISA only) ----------------
__device__ __forceinline__ uint32_t smem_u32(const void* p) {
    uint32_t a;
    asm("{ .reg .u64 t; cvta.to.shared.u64 t, %1; cvt.u32.u64 %0, t; }"
        : "=r"(a) : "l"(p));
    return a;
}
__device__ __forceinline__ void cp16(uint32_t saddr, const void* gptr) {
    asm volatile("cp.async.cg.shared.global [%0], [%1], 16;"
                 :: "r"(saddr), "l"(gptr) : "memory");
}
#define CP_COMMIT() asm volatile("cp.async.commit_group;" ::: "memory")
#define CP_WAIT(n)  asm volatile("cp.async.wait_group %0;" :: "n"(n) : "memory")

__device__ __forceinline__ uint32_t pack_bf16x2(float lo, float hi) {
    uint32_t r;
    asm("cvt.rn.bf16x2.f32 %0, %1, %2;" : "=r"(r) : "f"(hi), "f"(lo));
    return r;
}
__device__ __forceinline__ void ldsm4(uint32_t r[4], uint32_t addr) {
    asm volatile("ldmatrix.sync.aligned.m8n8.x4.shared.b16 {%0,%1,%2,%3}, [%4];"
                 : "=r"(r[0]), "=r"(r[1]), "=r"(r[2]), "=r"(r[3]) : "r"(addr));
}
__device__ __forceinline__ void mma16816(float c[4], const uint32_t a[4],
                                         uint32_t b0, uint32_t b1) {
    asm volatile(
        "mma.sync.aligned.m16n8k16.row.col.f32.bf16.bf16.f32 "
        "{%0,%1,%2,%3}, {%4,%5,%6,%7}, {%8,%9}, {%0,%1,%2,%3};"
        : "+f"(c[0]), "+f"(c[1]), "+f"(c[2]), "+f"(c[3])
        : "r"(a[0]), "r"(a[1]), "r"(a[2]), "r"(a[3]), "r"(b0), "r"(b1));
}
__device__ __forceinline__ uint32_t sw128(uint32_t off) {
    return off ^ ((off >> 3) & 0x70);
}

// ================= convert (f32 -> bf16) + norms =================
__global__ __launch_bounds__(256) void convert_kernel(const float* __restrict__ Q,
                                                      const float* __restrict__ S) {
    int w = (blockIdx.x * blockDim.x + threadIdx.x) >> 5;
    int lane = threadIdx.x & 31;
    if (w >= QF + SF) return;
    bool isQ = (w < QF);
    int r = isQ ? w : (w - QF);
    const float4* src = (const float4*)((isQ ? Q : S) + (size_t)r * DD);  // 144/row
    uint2* dst = (uint2*)((isQ ? g_Qh : g_Sh) + (size_t)r * DD);
    float s = 0.f;
#pragma unroll
    for (int j = 0; j < 4; j++) {
        int k = lane + 32 * j;
        float4 v = src[k];
        s = fmaf(v.x, v.x, fmaf(v.y, v.y, fmaf(v.z, v.z, fmaf(v.w, v.w, s))));
        uint2 o;
        o.x = pack_bf16x2(v.x, v.y);
        o.y = pack_bf16x2(v.z, v.w);
        dst[k] = o;
    }
    if (lane < 16) {
        int k = 128 + lane;
        float4 v = src[k];
        s = fmaf(v.x, v.x, fmaf(v.y, v.y, fmaf(v.z, v.z, fmaf(v.w, v.w, s))));
        uint2 o;
        o.x = pack_bf16x2(v.x, v.y);
        o.y = pack_bf16x2(v.z, v.w);
        dst[k] = o;
    }
#pragma unroll
    for (int o = 16; o > 0; o >>= 1) s += __shfl_down_sync(0xffffffffu, s, o);
    if (lane == 0) {
        float n = sqrtf(s);
        if (isQ) g_qn[r] = n;
        else     g_sn[r] = n;
    }
}

// ================= OTAM DP =================
__device__ __forceinline__ float softmin2(float a, float b) {
    float m = fminf(a, b);
    float s = __expf((m - a) * 2.f) + __expf((m - b) * 2.f);
    return fmaf(-0.5f, __logf(s), m);
}
__device__ __forceinline__ float softmin3(float a, float b, float c) {
    float m = fminf(fminf(a, b), c);
    float s = __expf((m - a) * 2.f) + __expf((m - b) * 2.f) + __expf((m - c) * 2.f);
    return fmaf(-0.5f, __logf(s), m);
}
template <int LSTRIDE, int SSTRIDE>
__device__ __forceinline__ float otam_dp(const float* __restrict__ d) {
    float prev[10];
    prev[0] = 0.f;
    float run = 0.f;
#pragma unroll
    for (int m = 1; m <= 8; m++) {
        run += d[(m - 1) * SSTRIDE];
        prev[m] = run;
    }
    prev[9] = run;
#pragma unroll
    for (int l = 1; l < 8; l++) {
        float cur[10];
        cur[0] = 0.f;
        cur[1] = d[l * LSTRIDE] + softmin3(prev[0], cur[0], prev[1]);
#pragma unroll
        for (int m = 2; m <= 8; m++)
            cur[m] = d[l * LSTRIDE + (m - 1) * SSTRIDE] +
                     softmin2(prev[m - 1], cur[m - 1]);
        cur[9] = softmin3(prev[8], cur[8], prev[9]);
#pragma unroll
        for (int m = 0; m < 10; m++) prev[m] = cur[m];
    }
    return prev[9];
}

// ================= fused GEMM + epilogue + DP =================
__global__ __launch_bounds__(256, 2) void fused_kernel(float* __restrict__ out) {
    extern __shared__ char smem[];
    const uint32_t sb = smem_u32(smem);
    float* sqn = (float*)smem;            // [128]
    float* ssn = (float*)(smem + 512);    // [128]
    const uint32_t stg = sb + SMEM_NORMS; // stages base (smem addr)
    const int tid = threadIdx.x;
    const int wid = tid >> 5;
    const int lane = tid & 31;
    const int bcol = blockIdx.x * N_TILE;  // support-frame base
    const int brow = blockIdx.y * M_TILE;  // query-frame base

    // stage norms
    if (tid < 128) sqn[tid] = g_qn[brow + tid];
    else           ssn[tid - 128] = g_sn[bcol + tid - 128];

    // per-thread cp.async source/dest (8 x 16B per chunk; idx = tid + i*256)
    const char* qsrc = (const char*)(g_Qh + (size_t)brow * DD);
    const char* ssrc = (const char*)(g_Sh + (size_t)bcol * DD);

    // warp tiling: wm in {0,1} (m-64 groups), wn in 0..3 (n-32 groups)
    const int wm = wid & 1;
    const int wn = wid >> 1;

    float acc[4][4][4];
#pragma unroll
    for (int i = 0; i < 4; i++)
#pragma unroll
        for (int j = 0; j < 4; j++)
#pragma unroll
            for (int k = 0; k < 4; k++) acc[i][j][k] = 0.f;

    // ---- issue chunk 0 ----
    {
        const int c = 0, s = 0;
#pragma unroll
        for (int i = 0; i < 8; i++) {
            int idx = tid + i * 256;       // 0..2047
            int r = idx & 127, v = (idx >> 7) & 7;
            bool isA = idx < 1024;
            uint32_t dst = stg + s * STAGE_BYTES + (isA ? 0 : M_TILE * 128) +
                           sw128(r * 128 + v * 16);
            const char* src = (isA ? qsrc : ssrc) +
                              (size_t)r * (DD * 2) + c * (KC * 2) + v * 16;
            cp16(dst, src);
        }
        CP_COMMIT();
    }

    for (int c = 0; c < NCHUNK; c++) {
        const int s = c & 1;
        if (c + 1 < NCHUNK) {
            const int s2 = (c + 1) & 1;
#pragma unroll
            for (int i = 0; i < 8; i++) {
                int idx = tid + i * 256;
                int r = idx & 127, v = (idx >> 7) & 7;
                bool isA = idx < 1024;
                uint32_t dst = stg + s2 * STAGE_BYTES + (isA ? 0 : M_TILE * 128) +
                               sw128(r * 128 + v * 16);
                const char* src = (isA ? qsrc : ssrc) +
                                  (size_t)r * (DD * 2) + (c + 1) * (KC * 2) + v * 16;
                cp16(dst, src);
            }
            CP_COMMIT();
            CP_WAIT(1);
        } else {
            CP_WAIT(0);
        }
        __syncthreads();

        const uint32_t Ab = stg + s * STAGE_BYTES;
        const uint32_t Bb = Ab + M_TILE * 128;
#pragma unroll
        for (int ks = 0; ks < 4; ks++) {   // 4 x K=16 per chunk
            uint32_t a[4][4];
#pragma unroll
            for (int fm = 0; fm < 4; fm++) {
                int row = wm * 64 + fm * 16 + (lane & 15);
                uint32_t off = row * 128 + ks * 32 + ((lane >> 4) & 1) * 16;
                ldsm4(a[fm], Ab + sw128(off));
            }
            uint32_t b[2][4];
#pragma unroll
            for (int p = 0; p < 2; p++) {  // each x4 covers two n8 frags
                int n = wn * 32 + p * 16 + (lane & 7) + ((lane >> 4) & 1) * 8;
                uint32_t off = n * 128 + ks * 32 + ((lane >> 3) & 1) * 16;
                ldsm4(b[p], Bb + sw128(off));
            }
#pragma unroll
            for (int fm = 0; fm < 4; fm++) {
                mma16816(acc[fm][0], a[fm], b[0][0], b[0][1]);
                mma16816(acc[fm][1], a[fm], b[0][2], b[0][3]);
                mma16816(acc[fm][2], a[fm], b[1][0], b[1][1]);
                mma16816(acc[fm][3], a[fm], b[1][2], b[1][3]);
            }
        }
        __syncthreads();  // all reads of stage s done before it is refilled
    }

    // ---- epilogue: normalized dists into smem [128][129] ----
    float* sdist = (float*)(smem + SMEM_NORMS);
    const int gid = lane >> 2;          // 0..7
    const int tc  = (lane & 3) * 2;
#pragma unroll
    for (int fm = 0; fm < 4; fm++) {
        int r0 = wm * 64 + fm * 16 + gid;
        float qn0 = sqn[r0], qn1 = sqn[r0 + 8];
#pragma unroll
        for (int fn = 0; fn < 4; fn++) {
            int c0 = wn * 32 + fn * 8 + tc;
            float sn0 = ssn[c0], sn1 = ssn[c0 + 1];
            float* a = acc[fm][fn];
            sdist[r0 * 129 + c0]           = 1.f - __fdividef(a[0], fmaf(qn0, sn0, EPSILON));
            sdist[r0 * 129 + c0 + 1]       = 1.f - __fdividef(a[1], fmaf(qn0, sn1, EPSILON));
            sdist[(r0 + 8) * 129 + c0]     = 1.f - __fdividef(a[2], fmaf(qn1, sn0, EPSILON));
            sdist[(r0 + 8) * 129 + c0 + 1] = 1.f - __fdividef(a[3], fmaf(qn1, sn1, EPSILON));
        }
    }
    __syncthreads();

    // ---- OTAM DP: 256 threads = 16 queries x 16 classes ----
    const int ql = tid >> 4;
    const int cl = tid & 15;
    const float* dbase = sdist + (ql * 8) * 129 + cl * 8;
    float r1 = otam_dp<129, 1>(dbase);
    float r2 = otam_dp<1, 129>(dbase);
    out[(blockIdx.y * 16 + ql) * NS + (blockIdx.x * 16 + cl)] = -(r1 + r2);
}

// ================= launch =================
extern "C" void kernel_launch(void* const* d_in, const int* in_sizes, int n_in,
                              void* d_out, int out_size) {
    const float* sup = (const float*)d_in[0];
    const float* qry = (const float*)d_in[1];
    if (n_in >= 2 && in_sizes[0] > in_sizes[1]) {
        const float* t = sup; sup = qry; qry = t;
    }
    float* out = (float*)d_out;

    // 1) convert to bf16 + exact f32 norms (one warp per row)
    {
        int warps = QF + SF;                    // 16896
        convert_kernel<<<(warps + 7) / 8, 256>>>(qry, sup);
    }
    // 2) fused tensor-core GEMM + normalize + OTAM DP
    {
        cudaFuncSetAttribute(fused_kernel,
                             cudaFuncAttributeMaxDynamicSharedMemorySize, SMEM_TOTAL);
        dim3 grid(SF / N_TILE, QF / M_TILE);    // (4, 128)
        fused_kernel<<<grid, 256, SMEM_TOTAL>>>(out);
    }
}

// round 6
// speedup vs baseline: 4.8963x; 1.2001x over previous
#include <cuda_runtime.h>
#include <cuda_bf16.h>
#include <math.h>
#include <stdint.h>

// ---------------- problem shapes ----------------
#define NQ 2048
#define NS 64
#define LL 8
#define DD 576
#define QF (NQ * LL)   // 16384 query frames
#define SF (NS * LL)   // 512 support frames
#define EPSILON 0.01f

// ---------------- GEMM tiling ----------------
#define M_TILE 128
#define N_TILE 128
#define KC 64                               // bf16 K-elems per chunk: 128B rows
#define NCHUNK (DD / KC)                    // 9
#define NSTAGE 3
#define STAGE_BYTES (M_TILE * 128 + N_TILE * 128)   // 32 KB (A then B)
#define SMEM_NORMS 1024                     // sqn[128] + ssn[128]
#define DSTRIDE 132                         // dist row stride (floats, 16B-aligned)
#define SMEM_STAGES (NSTAGE * STAGE_BYTES)          // 98304
#define SMEM_TOTAL (SMEM_NORMS + SMEM_STAGES)       // 99328 (dist 128*132*4=67584 fits under)

// ---------------- scratch (device globals) ----------------
__device__ __nv_bfloat16 g_Qh[(size_t)QF * DD];
__device__ __nv_bfloat16 g_Sh[(size_t)SF * DD];
__device__ float g_qn[QF];
__device__ float g_sn[SF];

// ---------------- PTX helpers (baseline ISA only) ----------------
__device__ __forceinline__ uint32_t smem_u32(const void* p) {
    uint32_t a;
    asm("{ .reg .u64 t; cvta.to.shared.u64 t, %1; cvt.u32.u64 %0, t; }"
        : "=r"(a) : "l"(p));
    return a;
}
__device__ __forceinline__ void cp16(uint32_t saddr, const void* gptr) {
    asm volatile("cp.async.cg.shared.global [%0], [%1], 16;"
                 :: "r"(saddr), "l"(gptr) : "memory");
}
#define CP_COMMIT() asm volatile("cp.async.commit_group;" ::: "memory")
#define CP_WAIT(n)  asm volatile("cp.async.wait_group %0;" :: "n"(n) : "memory")

__device__ __forceinline__ uint32_t pack_bf16x2(float lo, float hi) {
    uint32_t r;
    asm("cvt.rn.bf16x2.f32 %0, %1, %2;" : "=r"(r) : "f"(hi), "f"(lo));
    return r;
}
__device__ __forceinline__ void ldsm4(uint32_t r[4], uint32_t addr) {
    asm volatile("ldmatrix.sync.aligned.m8n8.x4.shared.b16 {%0,%1,%2,%3}, [%4];"
                 : "=r"(r[0]), "=r"(r[1]), "=r"(r[2]), "=r"(r[3]) : "r"(addr));
}
__device__ __forceinline__ void mma16816(float c[4], const uint32_t a[4],
                                         uint32_t b0, uint32_t b1) {
    asm volatile(
        "mma.sync.aligned.m16n8k16.row.col.f32.bf16.bf16.f32 "
        "{%0,%1,%2,%3}, {%4,%5,%6,%7}, {%8,%9}, {%0,%1,%2,%3};"
        : "+f"(c[0]), "+f"(c[1]), "+f"(c[2]), "+f"(c[3])
        : "r"(a[0]), "r"(a[1]), "r"(a[2]), "r"(a[3]), "r"(b0), "r"(b1));
}
__device__ __forceinline__ uint32_t sw128(uint32_t off) {
    return off ^ ((off >> 3) & 0x70);
}
__device__ __forceinline__ float ex2f(float x) {
    float y; asm("ex2.approx.ftz.f32 %0, %1;" : "=f"(y) : "f"(x)); return y;
}
__device__ __forceinline__ float lg2f(float x) {
    float y; asm("lg2.approx.ftz.f32 %0, %1;" : "=f"(y) : "f"(x)); return y;
}

// ================= convert (f32 -> bf16) + norms =================
__global__ __launch_bounds__(256) void convert_kernel(const float* __restrict__ Q,
                                                      const float* __restrict__ S) {
    int w = (blockIdx.x * blockDim.x + threadIdx.x) >> 5;
    int lane = threadIdx.x & 31;
    if (w >= QF + SF) return;
    bool isQ = (w < QF);
    int r = isQ ? w : (w - QF);
    const float4* src = (const float4*)((isQ ? Q : S) + (size_t)r * DD);  // 144/row
    uint2* dst = (uint2*)((isQ ? g_Qh : g_Sh) + (size_t)r * DD);
    float s = 0.f;
#pragma unroll
    for (int j = 0; j < 4; j++) {
        int k = lane + 32 * j;
        float4 v = src[k];
        s = fmaf(v.x, v.x, fmaf(v.y, v.y, fmaf(v.z, v.z, fmaf(v.w, v.w, s))));
        uint2 o;
        o.x = pack_bf16x2(v.x, v.y);
        o.y = pack_bf16x2(v.z, v.w);
        dst[k] = o;
    }
    if (lane < 16) {
        int k = 128 + lane;
        float4 v = src[k];
        s = fmaf(v.x, v.x, fmaf(v.y, v.y, fmaf(v.z, v.z, fmaf(v.w, v.w, s))));
        uint2 o;
        o.x = pack_bf16x2(v.x, v.y);
        o.y = pack_bf16x2(v.z, v.w);
        dst[k] = o;
    }
#pragma unroll
    for (int o = 16; o > 0; o >>= 1) s += __shfl_down_sync(0xffffffffu, s, o);
    if (lane == 0) {
        float n = sqrtf(s);
        if (isQ) g_qn[r] = n;
        else     g_sn[r] = n;
    }
}

// ================= OTAM DP (MUFU-lean softmins) =================
// softmin_{lbda=0.5}(x...) = m - 0.5*ln(sum e^{-2(x-m)}), m = min.
// The min term's exponential is exactly 1 -> skip one ex2.
#define CEXP 2.885390081777927f   // 2/ln2
#define CLOG 0.346573590279973f   // 0.5*ln2
__device__ __forceinline__ float softmin2(float a, float b) {
    float m = fminf(a, b), x = fmaxf(a, b);
    float s = 1.f + ex2f(CEXP * (m - x));
    return fmaf(-CLOG, lg2f(s), m);
}
__device__ __forceinline__ float softmin3(float a, float b, float c) {
    float m = fminf(fminf(a, b), c);
    float x = fmaxf(fmaxf(a, b), c);
    float mid = ((a + b) + c) - m - x;     // exact: the remaining term
    float s = 1.f + ex2f(CEXP * (m - mid)) + ex2f(CEXP * (m - x));
    return fmaf(-CLOG, lg2f(s), m);
}
// d(l, m) = d[l*LS + m*SS] over a register-resident 8x8 block.
template <int LS, int SS>
__device__ __forceinline__ float otam_dp(const float* __restrict__ d) {
    float prev[10];
    prev[0] = 0.f;
    float run = 0.f;
#pragma unroll
    for (int m = 1; m <= 8; m++) {
        run += d[(m - 1) * SS];
        prev[m] = run;
    }
    prev[9] = run;
#pragma unroll
    for (int l = 1; l < 8; l++) {
        float cur[10];
        cur[0] = 0.f;
        cur[1] = d[l * LS] + softmin3(prev[0], cur[0], prev[1]);
#pragma unroll
        for (int m = 2; m <= 8; m++)
            cur[m] = d[l * LS + (m - 1) * SS] + softmin2(prev[m - 1], cur[m - 1]);
        cur[9] = softmin3(prev[8], cur[8], prev[9]);
#pragma unroll
        for (int m = 0; m < 10; m++) prev[m] = cur[m];
    }
    return prev[9];
}

// ================= fused GEMM + epilogue + DP =================
__device__ __forceinline__ void issue_chunk(uint32_t stg, int stage, int c,
                                            const char* qsrc, const char* ssrc,
                                            int tid) {
#pragma unroll
    for (int i = 0; i < 8; i++) {
        int idx = tid + i * 256;            // 0..2047
        int r = idx & 127, v = (idx >> 7) & 7;
        bool isA = idx < 1024;
        uint32_t dst = stg + stage * STAGE_BYTES + (isA ? 0 : M_TILE * 128) +
                       sw128(r * 128 + v * 16);
        const char* src = (isA ? qsrc : ssrc) +
                          (size_t)r * (DD * 2) + c * (KC * 2) + v * 16;
        cp16(dst, src);
    }
    CP_COMMIT();
}

__device__ __forceinline__ void compute_chunk(uint32_t Ab, uint32_t Bb,
                                              float acc[4][4][4],
                                              int wm, int wn, int lane) {
#pragma unroll
    for (int ks = 0; ks < 4; ks++) {        // 4 x K=16 per 64-elem chunk
        uint32_t a[4][4];
#pragma unroll
        for (int fm = 0; fm < 4; fm++) {
            int row = wm * 64 + fm * 16 + (lane & 15);
            uint32_t off = row * 128 + ks * 32 + ((lane >> 4) & 1) * 16;
            ldsm4(a[fm], Ab + sw128(off));
        }
        uint32_t b[2][4];
#pragma unroll
        for (int p = 0; p < 2; p++) {
            int n = wn * 32 + p * 16 + (lane & 7) + ((lane >> 4) & 1) * 8;
            uint32_t off = n * 128 + ks * 32 + ((lane >> 3) & 1) * 16;
            ldsm4(b[p], Bb + sw128(off));
        }
#pragma unroll
        for (int fm = 0; fm < 4; fm++) {
            mma16816(acc[fm][0], a[fm], b[0][0], b[0][1]);
            mma16816(acc[fm][1], a[fm], b[0][2], b[0][3]);
            mma16816(acc[fm][2], a[fm], b[1][0], b[1][1]);
            mma16816(acc[fm][3], a[fm], b[1][2], b[1][3]);
        }
    }
}

__global__ __launch_bounds__(256, 2) void fused_kernel(float* __restrict__ out) {
    extern __shared__ char smem[];
    const uint32_t sb = smem_u32(smem);
    float* sqn = (float*)smem;            // [128]
    float* ssn = (float*)(smem + 512);    // [128]
    const uint32_t stg = sb + SMEM_NORMS;
    const int tid = threadIdx.x;
    const int wid = tid >> 5;
    const int lane = tid & 31;
    const int bcol = blockIdx.x * N_TILE;
    const int brow = blockIdx.y * M_TILE;

    if (tid < 128) sqn[tid] = g_qn[brow + tid];
    else           ssn[tid - 128] = g_sn[bcol + tid - 128];

    const char* qsrc = (const char*)(g_Qh + (size_t)brow * DD);
    const char* ssrc = (const char*)(g_Sh + (size_t)bcol * DD);

    const int wm = wid & 1;
    const int wn = wid >> 1;

    float acc[4][4][4];
#pragma unroll
    for (int i = 0; i < 4; i++)
#pragma unroll
        for (int j = 0; j < 4; j++)
#pragma unroll
            for (int k = 0; k < 4; k++) acc[i][j][k] = 0.f;

    // ---- prologue: stages 0 and 1 in flight ----
    issue_chunk(stg, 0, 0, qsrc, ssrc, tid);
    issue_chunk(stg, 1, 1, qsrc, ssrc, tid);

    // ---- main loop: one barrier per chunk, loads lead compute by 2 ----
#pragma unroll 1
    for (int c = 0; c < NCHUNK - 1; c++) {
        CP_WAIT(1);                         // chunk c landed
        __syncthreads();                    // visible to all; stage (c-1)%3 free
        const int s = c % NSTAGE;
        compute_chunk(stg + s * STAGE_BYTES,
                      stg + s * STAGE_BYTES + M_TILE * 128, acc, wm, wn, lane);
        if (c + 2 < NCHUNK)
            issue_chunk(stg, (c + 2) % NSTAGE, c + 2, qsrc, ssrc, tid);
    }
    {   // final chunk
        CP_WAIT(0);
        __syncthreads();
        const int s = (NCHUNK - 1) % NSTAGE;
        compute_chunk(stg + s * STAGE_BYTES,
                      stg + s * STAGE_BYTES + M_TILE * 128, acc, wm, wn, lane);
    }
    __syncthreads();   // everyone done reading stages before dist overlay

    // ---- epilogue: normalized dists into smem [128][DSTRIDE] ----
    float* sdist = (float*)(smem + SMEM_NORMS);
    const int gid = lane >> 2;
    const int tc  = (lane & 3) * 2;
#pragma unroll
    for (int fm = 0; fm < 4; fm++) {
        int r0 = wm * 64 + fm * 16 + gid;
        float qn0 = sqn[r0], qn1 = sqn[r0 + 8];
#pragma unroll
        for (int fn = 0; fn < 4; fn++) {
            int c0 = wn * 32 + fn * 8 + tc;
            float sn0 = ssn[c0], sn1 = ssn[c0 + 1];
            float* a = acc[fm][fn];
            float2 v0 = make_float2(1.f - __fdividef(a[0], fmaf(qn0, sn0, EPSILON)),
                                    1.f - __fdividef(a[1], fmaf(qn0, sn1, EPSILON)));
            float2 v1 = make_float2(1.f - __fdividef(a[2], fmaf(qn1, sn0, EPSILON)),
                                    1.f - __fdividef(a[3], fmaf(qn1, sn1, EPSILON)));
            *(float2*)&sdist[r0 * DSTRIDE + c0] = v0;
            *(float2*)&sdist[(r0 + 8) * DSTRIDE + c0] = v1;
        }
    }
    __syncthreads();

    // ---- OTAM DP: 256 threads = 16 queries x 16 classes, block in regs ----
    const int ql = tid >> 4;
    const int cl = tid & 15;
    float dreg[64];
#pragma unroll
    for (int l = 0; l < 8; l++) {
        const float* rp = &sdist[(ql * 8 + l) * DSTRIDE + cl * 8];
        float4 u = *(const float4*)rp;
        float4 w = *(const float4*)(rp + 4);
        dreg[l * 8 + 0] = u.x; dreg[l * 8 + 1] = u.y;
        dreg[l * 8 + 2] = u.z; dreg[l * 8 + 3] = u.w;
        dreg[l * 8 + 4] = w.x; dreg[l * 8 + 5] = w.y;
        dreg[l * 8 + 6] = w.z; dreg[l * 8 + 7] = w.w;
    }
    float r1 = otam_dp<8, 1>(dreg);
    float r2 = otam_dp<1, 8>(dreg);
    out[(blockIdx.y * 16 + ql) * NS + (blockIdx.x * 16 + cl)] = -(r1 + r2);
}

// ================= launch =================
extern "C" void kernel_launch(void* const* d_in, const int* in_sizes, int n_in,
                              void* d_out, int out_size) {
    const float* sup = (const float*)d_in[0];
    const float* qry = (const float*)d_in[1];
    if (n_in >= 2 && in_sizes[0] > in_sizes[1]) {
        const float* t = sup; sup = qry; qry = t;
    }
    float* out = (float*)d_out;

    {
        int warps = QF + SF;                    // 16896
        convert_kernel<<<(warps + 7) / 8, 256>>>(qry, sup);
    }
    {
        cudaFuncSetAttribute(fused_kernel,
                             cudaFuncAttributeMaxDynamicSharedMemorySize, SMEM_TOTAL);
        dim3 grid(SF / N_TILE, QF / M_TILE);    // (4, 128)
        fused_kernel<<<grid, 256, SMEM_TOTAL>>>(out);
    }
}

// round 7
// speedup vs baseline: 7.0969x; 1.4494x over previous
#include <cuda_runtime.h>
#include <cuda_bf16.h>
#include <math.h>
#include <stdint.h>

// ---------------- problem shapes ----------------
#define NQ 2048
#define NS 64
#define LL 8
#define DD 576
#define QF (NQ * LL)   // 16384 query frames
#define SF (NS * LL)   // 512 support frames
#define EPSILON 0.01f

// ---------------- GEMM tiling ----------------
#define M_TILE 128
#define N_TILE 64
#define KC 64                                // bf16 K-elems per chunk: 128B rows
#define NCHUNK (DD / KC)                     // 9
#define NSTAGE 3
#define A_STAGE (M_TILE * 128)               // 16384
#define B_STAGE (N_TILE * 128)               // 8192
#define STAGE_BYTES (A_STAGE + B_STAGE)      // 24576
#define SMEM_NORMS 1024
#define DSTRIDE 68                           // dist row stride (floats, 16B-aligned)
#define SMEM_TOTAL (SMEM_NORMS + NSTAGE * STAGE_BYTES)  // 74752; x3 CTAs = 224256

// ---------------- scratch (device globals) ----------------
__device__ __nv_bfloat16 g_Qh[(size_t)QF * DD];
__device__ __nv_bfloat16 g_Sh[(size_t)SF * DD];
__device__ float g_qn[QF];
__device__ float g_sn[SF];

// ---------------- PTX helpers ----------------
__device__ __forceinline__ uint32_t smem_u32(const void* p) {
    uint32_t a;
    asm("{ .reg .u64 t; cvta.to.shared.u64 t, %1; cvt.u32.u64 %0, t; }"
        : "=r"(a) : "l"(p));
    return a;
}
__device__ __forceinline__ void cp16(uint32_t saddr, const void* gptr) {
    asm volatile("cp.async.cg.shared.global [%0], [%1], 16;"
                 :: "r"(saddr), "l"(gptr) : "memory");
}
#define CP_COMMIT() asm volatile("cp.async.commit_group;" ::: "memory")
#define CP_WAIT(n)  asm volatile("cp.async.wait_group %0;" :: "n"(n) : "memory")

__device__ __forceinline__ uint32_t pack_bf16x2(float lo, float hi) {
    uint32_t r;
    asm("cvt.rn.bf16x2.f32 %0, %1, %2;" : "=r"(r) : "f"(hi), "f"(lo));
    return r;
}
__device__ __forceinline__ void ldsm4(uint32_t r[4], uint32_t addr) {
    asm volatile("ldmatrix.sync.aligned.m8n8.x4.shared.b16 {%0,%1,%2,%3}, [%4];"
                 : "=r"(r[0]), "=r"(r[1]), "=r"(r[2]), "=r"(r[3]) : "r"(addr));
}
__device__ __forceinline__ void mma16816(float c[4], const uint32_t a[4],
                                         uint32_t b0, uint32_t b1) {
    asm volatile(
        "mma.sync.aligned.m16n8k16.row.col.f32.bf16.bf16.f32 "
        "{%0,%1,%2,%3}, {%4,%5,%6,%7}, {%8,%9}, {%0,%1,%2,%3};"
        : "+f"(c[0]), "+f"(c[1]), "+f"(c[2]), "+f"(c[3])
        : "r"(a[0]), "r"(a[1]), "r"(a[2]), "r"(a[3]), "r"(b0), "r"(b1));
}
__device__ __forceinline__ uint32_t sw128(uint32_t off) {
    return off ^ ((off >> 3) & 0x70);
}
__device__ __forceinline__ float ex2f(float x) {
    float y; asm("ex2.approx.ftz.f32 %0, %1;" : "=f"(y) : "f"(x)); return y;
}
__device__ __forceinline__ float lg2f(float x) {
    float y; asm("lg2.approx.ftz.f32 %0, %1;" : "=f"(y) : "f"(x)); return y;
}

// ================= convert (f32 -> bf16) + norms =================
__global__ __launch_bounds__(256) void convert_kernel(const float* __restrict__ Q,
                                                      const float* __restrict__ S) {
    int w = (blockIdx.x * blockDim.x + threadIdx.x) >> 5;
    int lane = threadIdx.x & 31;
    if (w >= QF + SF) return;
    bool isQ = (w < QF);
    int r = isQ ? w : (w - QF);
    const float4* src = (const float4*)((isQ ? Q : S) + (size_t)r * DD);  // 144/row
    uint2* dst = (uint2*)((isQ ? g_Qh : g_Sh) + (size_t)r * DD);
    float s = 0.f;
#pragma unroll
    for (int j = 0; j < 4; j++) {
        int k = lane + 32 * j;
        float4 v = src[k];
        s = fmaf(v.x, v.x, fmaf(v.y, v.y, fmaf(v.z, v.z, fmaf(v.w, v.w, s))));
        uint2 o;
        o.x = pack_bf16x2(v.x, v.y);
        o.y = pack_bf16x2(v.z, v.w);
        dst[k] = o;
    }
    if (lane < 16) {
        int k = 128 + lane;
        float4 v = src[k];
        s = fmaf(v.x, v.x, fmaf(v.y, v.y, fmaf(v.z, v.z, fmaf(v.w, v.w, s))));
        uint2 o;
        o.x = pack_bf16x2(v.x, v.y);
        o.y = pack_bf16x2(v.z, v.w);
        dst[k] = o;
    }
#pragma unroll
    for (int o = 16; o > 0; o >>= 1) s += __shfl_down_sync(0xffffffffu, s, o);
    if (lane == 0) {
        float n = sqrtf(s);
        if (isQ) g_qn[r] = n;
        else     g_sn[r] = n;
    }
}

// ================= OTAM DP (MUFU-lean softmins) =================
#define CEXP 2.885390081777927f   // 2/ln2
#define CLOG 0.346573590279973f   // 0.5*ln2
__device__ __forceinline__ float softmin2(float a, float b) {
    float m = fminf(a, b), x = fmaxf(a, b);
    float s = 1.f + ex2f(CEXP * (m - x));
    return fmaf(-CLOG, lg2f(s), m);
}
__device__ __forceinline__ float softmin3(float a, float b, float c) {
    float m = fminf(fminf(a, b), c);
    float x = fmaxf(fmaxf(a, b), c);
    float mid = ((a + b) + c) - m - x;
    float s = 1.f + ex2f(CEXP * (m - mid)) + ex2f(CEXP * (m - x));
    return fmaf(-CLOG, lg2f(s), m);
}
template <int LS, int SS>
__device__ __forceinline__ float otam_dp(const float* __restrict__ d) {
    float prev[10];
    prev[0] = 0.f;
    float run = 0.f;
#pragma unroll
    for (int m = 1; m <= 8; m++) {
        run += d[(m - 1) * SS];
        prev[m] = run;
    }
    prev[9] = run;
#pragma unroll
    for (int l = 1; l < 8; l++) {
        float cur[10];
        cur[0] = 0.f;
        cur[1] = d[l * LS] + softmin3(prev[0], cur[0], prev[1]);
#pragma unroll
        for (int m = 2; m <= 8; m++)
            cur[m] = d[l * LS + (m - 1) * SS] + softmin2(prev[m - 1], cur[m - 1]);
        cur[9] = softmin3(prev[8], cur[8], prev[9]);
#pragma unroll
        for (int m = 0; m < 10; m++) prev[m] = cur[m];
    }
    return prev[9];
}

// ================= fused GEMM + epilogue + DP =================
struct Frags { uint32_t a[2][4]; uint32_t b[2][4]; };

__device__ __forceinline__ void load_frags(Frags& f, uint32_t Ab, uint32_t Bb,
                                           int ks, int wm, int wn, int lane) {
#pragma unroll
    for (int fm = 0; fm < 2; fm++) {
        int row = wm * 32 + fm * 16 + (lane & 15);
        uint32_t off = row * 128 + ks * 32 + ((lane >> 4) & 1) * 16;
        ldsm4(f.a[fm], Ab + sw128(off));
    }
#pragma unroll
    for (int p = 0; p < 2; p++) {
        int n = wn * 32 + p * 16 + (lane & 7) + ((lane >> 4) & 1) * 8;
        uint32_t off = n * 128 + ks * 32 + ((lane >> 3) & 1) * 16;
        ldsm4(f.b[p], Bb + sw128(off));
    }
}
__device__ __forceinline__ void mma_frags(float acc[2][4][4], const Frags& f) {
#pragma unroll
    for (int fm = 0; fm < 2; fm++) {
        mma16816(acc[fm][0], f.a[fm], f.b[0][0], f.b[0][1]);
        mma16816(acc[fm][1], f.a[fm], f.b[0][2], f.b[0][3]);
        mma16816(acc[fm][2], f.a[fm], f.b[1][0], f.b[1][1]);
        mma16816(acc[fm][3], f.a[fm], f.b[1][2], f.b[1][3]);
    }
}

// 1536 x 16B vectors per chunk (A 1024 + B 512); 6 per thread, coalesced:
// 8 consecutive threads cover one contiguous 128B row.
__device__ __forceinline__ void issue_chunk(uint32_t stg, int stage, int c,
                                            const char* qsrc, const char* ssrc,
                                            int tid) {
#pragma unroll
    for (int i = 0; i < 6; i++) {
        int idx = tid + i * 256;            // 0..1535
        bool isA = idx < 1024;
        int j = isA ? idx : (idx - 1024);
        int r = j >> 3, v = j & 7;
        uint32_t dst = stg + stage * STAGE_BYTES + (isA ? 0 : A_STAGE) +
                       sw128(r * 128 + v * 16);
        const char* src = (isA ? qsrc : ssrc) +
                          (size_t)r * (DD * 2) + c * (KC * 2) + v * 16;
        cp16(dst, src);
    }
    CP_COMMIT();
}

__global__ __launch_bounds__(256, 3) void fused_kernel(float* __restrict__ out) {
    extern __shared__ char smem[];
    const uint32_t sb = smem_u32(smem);
    float* sqn = (float*)smem;            // [128]
    float* ssn = (float*)(smem + 512);    // [64]
    const uint32_t stg = sb + SMEM_NORMS;
    const int tid = threadIdx.x;
    const int wid = tid >> 5;
    const int lane = tid & 31;
    const int bcol = blockIdx.x * N_TILE;
    const int brow = blockIdx.y * M_TILE;

    if (tid < 128) sqn[tid] = g_qn[brow + tid];
    else if (tid < 192) ssn[tid - 128] = g_sn[bcol + tid - 128];

    const char* qsrc = (const char*)(g_Qh + (size_t)brow * DD);
    const char* ssrc = (const char*)(g_Sh + (size_t)bcol * DD);

    const int wm = wid & 3;    // 4 m-groups of 32 rows
    const int wn = wid >> 2;   // 2 n-groups of 32 cols

    float acc[2][4][4];
#pragma unroll
    for (int i = 0; i < 2; i++)
#pragma unroll
        for (int j = 0; j < 4; j++)
#pragma unroll
            for (int k = 0; k < 4; k++) acc[i][j][k] = 0.f;

    issue_chunk(stg, 0, 0, qsrc, ssrc, tid);
    issue_chunk(stg, 1, 1, qsrc, ssrc, tid);

    Frags fr[2];
#pragma unroll 1
    for (int c = 0; c < NCHUNK; c++) {
        if (c < NCHUNK - 1) CP_WAIT(1); else CP_WAIT(0);
        __syncthreads();
        const int s = c % NSTAGE;
        const uint32_t Ab = stg + s * STAGE_BYTES;
        const uint32_t Bb = Ab + A_STAGE;
        load_frags(fr[0], Ab, Bb, 0, wm, wn, lane);
        if (c + 2 < NCHUNK)
            issue_chunk(stg, (c + 2) % NSTAGE, c + 2, qsrc, ssrc, tid);
#pragma unroll
        for (int ks = 0; ks < 4; ks++) {
            if (ks < 3) load_frags(fr[(ks + 1) & 1], Ab, Bb, ks + 1, wm, wn, lane);
            mma_frags(acc, fr[ks & 1]);
        }
    }
    __syncthreads();   // all stage reads done before dist overlay

    // ---- epilogue: normalized dists into smem [128][DSTRIDE] ----
    float* sdist = (float*)(smem + SMEM_NORMS);
    const int gid = lane >> 2;
    const int tc  = (lane & 3) * 2;
#pragma unroll
    for (int fm = 0; fm < 2; fm++) {
        int r0 = wm * 32 + fm * 16 + gid;
        float qn0 = sqn[r0], qn1 = sqn[r0 + 8];
#pragma unroll
        for (int fn = 0; fn < 4; fn++) {
            int c0 = wn * 32 + fn * 8 + tc;
            float sn0 = ssn[c0], sn1 = ssn[c0 + 1];
            float* a = acc[fm][fn];
            float2 v0 = make_float2(1.f - __fdividef(a[0], fmaf(qn0, sn0, EPSILON)),
                                    1.f - __fdividef(a[1], fmaf(qn0, sn1, EPSILON)));
            float2 v1 = make_float2(1.f - __fdividef(a[2], fmaf(qn1, sn0, EPSILON)),
                                    1.f - __fdividef(a[3], fmaf(qn1, sn1, EPSILON)));
            *(float2*)&sdist[r0 * DSTRIDE + c0] = v0;
            *(float2*)&sdist[(r0 + 8) * DSTRIDE + c0] = v1;
        }
    }
    __syncthreads();

    // ---- OTAM DP: 128 pairs (16 q x 8 c); warps 0-3 forward, 4-7 transposed ----
    const int pair = tid & 127;
    const int ql = pair >> 3;
    const int cl = pair & 7;
    float dreg[64];
#pragma unroll
    for (int l = 0; l < 8; l++) {
        const float* rp = &sdist[(ql * 8 + l) * DSTRIDE + cl * 8];
        float4 u = *(const float4*)rp;
        float4 w = *(const float4*)(rp + 4);
        dreg[l * 8 + 0] = u.x; dreg[l * 8 + 1] = u.y;
        dreg[l * 8 + 2] = u.z; dreg[l * 8 + 3] = u.w;
        dreg[l * 8 + 4] = w.x; dreg[l * 8 + 5] = w.y;
        dreg[l * 8 + 6] = w.z; dreg[l * 8 + 7] = w.w;
    }
    float* sres = (float*)smem;   // reuse norms region (128 floats)
    float r;
    if (tid >= 128) {             // warps 4-7: transposed DP
        r = otam_dp<1, 8>(dreg);
        sres[pair] = r;
    } else {                      // warps 0-3: forward DP
        r = otam_dp<8, 1>(dreg);
    }
    __syncthreads();
    if (tid < 128)
        out[(blockIdx.y * 16 + ql) * NS + (blockIdx.x * 8 + cl)] = -(r + sres[pair]);
}

// ================= launch =================
extern "C" void kernel_launch(void* const* d_in, const int* in_sizes, int n_in,
                              void* d_out, int out_size) {
    const float* sup = (const float*)d_in[0];
    const float* qry = (const float*)d_in[1];
    if (n_in >= 2 && in_sizes[0] > in_sizes[1]) {
        const float* t = sup; sup = qry; qry = t;
    }
    float* out = (float*)d_out;

    {
        int warps = QF + SF;                    // 16896
        convert_kernel<<<(warps + 7) / 8, 256>>>(qry, sup);
    }
    {
        cudaFuncSetAttribute(fused_kernel,
                             cudaFuncAttributeMaxDynamicSharedMemorySize, SMEM_TOTAL);
        dim3 grid(SF / N_TILE, QF / M_TILE);    // (8, 128)
        fused_kernel<<<grid, 256, SMEM_TOTAL>>>(out);
    }
}